// round 1
// baseline (speedup 1.0000x reference)
#include <cuda_runtime.h>
#include <math.h>

// ---------------- global scratch (no allocations allowed) ----------------
__device__ float q_g[4 * 1024 * 8];
__device__ float k_g[4 * 1024 * 8];
__device__ float v_g[4 * 1024 * 8];
__device__ float attn_g[1024 * 32];

#define NB 8

__device__ __forceinline__ float sigf(float x) { return 1.f / (1.f + __expf(-x)); }

// =====================================================================
// Kernel 1: embedding + pos-enc + LSTM1(32->64) + LSTM2(64->32) + residual
//           + qkv projection at final step. 128 CTAs x 256 thr, 8 batch/CTA.
// =====================================================================
__global__ void __launch_bounds__(256, 1) lstm_kernel(
    const float* __restrict__ x,
    const float* __restrict__ emb_w, const float* __restrict__ emb_b,
    const float* __restrict__ w1, const float* __restrict__ u1,
    const float* __restrict__ b1i, const float* __restrict__ b1h,
    const float* __restrict__ w2, const float* __restrict__ u2,
    const float* __restrict__ b2i, const float* __restrict__ b2h,
    const float* __restrict__ attn_w, const float* __restrict__ attn_b)
{
    extern __shared__ float sm[];
    float* wih1T = sm;              // [32][256]  8192
    float* whh1T = wih1T + 8192;    // [64][256] 16384
    float* wih2T = whh1T + 16384;   // [64][128]  8192
    float* whh2T = wih2T + 8192;    // [32][128]  4096
    float* bias1 = whh2T + 4096;    // 256
    float* bias2 = bias1 + 256;     // 128
    float* pe    = bias2 + 128;     // [16][32]   512
    float* xs    = pe + 512;        // [8][16]    128
    float* h1s   = xs + 128;        // [k=64][b=8] 512
    float* c1s   = h1s + 512;       // [b=8][64]  512
    float* h2s   = c1s + 512;       // [j=32][b=8] 256
    float* c2s   = h2s + 256;       // [b=8][32]  256
    float* embs  = c2s + 256;       // [e=32][b=8] 256
    float* g1s   = embs + 256;      // [b=8][256] 2048
    float* g2s   = g1s + 2048;      // [b=8][128] 1024

    const int tid = threadIdx.x;
    const int b0 = blockIdx.x * NB;

    // ---- load weights transposed into smem ----
    for (int i = tid; i < 256 * 32; i += 256) { int e = i >> 8, g = i & 255; wih1T[e * 256 + g] = w1[g * 32 + e]; }
    for (int i = tid; i < 256 * 64; i += 256) { int k = i >> 8, g = i & 255; whh1T[k * 256 + g] = u1[g * 64 + k]; }
    for (int i = tid; i < 128 * 64; i += 256) { int k = i >> 7, g = i & 127; wih2T[k * 128 + g] = w2[g * 64 + k]; }
    for (int i = tid; i < 128 * 32; i += 256) { int k = i >> 7, g = i & 127; whh2T[k * 128 + g] = u2[g * 32 + k]; }
    bias1[tid] = b1i[tid] + b1h[tid];
    if (tid < 128) bias2[tid] = b2i[tid] + b2h[tid];

    // ---- positional encoding table (16x32) ----
    for (int i = tid; i < 512; i += 256) {
        int t = i >> 5, e = i & 31;
        int half = e >> 1;
        float div = __expf(-(float)(2 * half) * (9.210340371976184f / 32.0f)); // ln(10000)=9.2103...
        float arg = (float)t * div;
        pe[i] = (e & 1) ? cosf(arg) : sinf(arg);
    }
    // ---- x slice ----
    for (int i = tid; i < NB * 16; i += 256) { int b = i >> 4, t = i & 15; xs[i] = x[(b0 + b) * 16 + t]; }
    // ---- init states ----
    for (int i = tid; i < 512; i += 256) { h1s[i] = 0.f; c1s[i] = 0.f; }
    h2s[tid & 255] = 0.f; c2s[tid & 255] = 0.f;
    __syncthreads();

    for (int t = 0; t < 16; ++t) {
        // ---- embedding for this step: thread (b,e) ----
        {
            int b = tid >> 5, e = tid & 31;
            embs[e * NB + b] = xs[b * 16 + t] * emb_w[e] + emb_b[e] + pe[t * 32 + e];
        }
        __syncthreads();

        // ---- LSTM1 gate pre-activations: thread = gate (256), 8 batches in regs ----
        {
            float acc[NB];
            float bv = bias1[tid];
            #pragma unroll
            for (int b = 0; b < NB; b++) acc[b] = bv;
            #pragma unroll 8
            for (int e = 0; e < 32; e++) {
                float w = wih1T[e * 256 + tid];
                float4 hA = *(const float4*)&embs[e * NB];
                float4 hB = *(const float4*)&embs[e * NB + 4];
                acc[0] += hA.x * w; acc[1] += hA.y * w; acc[2] += hA.z * w; acc[3] += hA.w * w;
                acc[4] += hB.x * w; acc[5] += hB.y * w; acc[6] += hB.z * w; acc[7] += hB.w * w;
            }
            #pragma unroll 8
            for (int k = 0; k < 64; k++) {
                float w = whh1T[k * 256 + tid];
                float4 hA = *(const float4*)&h1s[k * NB];
                float4 hB = *(const float4*)&h1s[k * NB + 4];
                acc[0] += hA.x * w; acc[1] += hA.y * w; acc[2] += hA.z * w; acc[3] += hA.w * w;
                acc[4] += hB.x * w; acc[5] += hB.y * w; acc[6] += hB.z * w; acc[7] += hB.w * w;
            }
            #pragma unroll
            for (int b = 0; b < NB; b++) g1s[b * 256 + tid] = acc[b];
        }
        __syncthreads();

        // ---- LSTM1 cell update: 512 (b,j) items ----
        #pragma unroll
        for (int r = 0; r < 2; r++) {
            int id = r * 256 + tid;
            int b = id >> 6, j = id & 63;
            float gi = g1s[b * 256 + j];
            float gf = g1s[b * 256 + 64 + j];
            float gg = g1s[b * 256 + 128 + j];
            float go = g1s[b * 256 + 192 + j];
            float c = c1s[b * 64 + j];
            float nc = sigf(gf) * c + sigf(gi) * tanhf(gg);
            float h = sigf(go) * tanhf(nc);
            c1s[b * 64 + j] = nc;
            h1s[j * NB + b] = h;
        }
        __syncthreads();

        // ---- LSTM2 gate pre-activations: thread = (bg, gate128), 4 batches in regs ----
        {
            int g = tid & 127;
            int bg = (tid >> 7) * 4;
            float acc[4];
            float bv = bias2[g];
            #pragma unroll
            for (int b = 0; b < 4; b++) acc[b] = bv;
            #pragma unroll 8
            for (int k = 0; k < 64; k++) {
                float w = wih2T[k * 128 + g];
                float4 hv = *(const float4*)&h1s[k * NB + bg];
                acc[0] += hv.x * w; acc[1] += hv.y * w; acc[2] += hv.z * w; acc[3] += hv.w * w;
            }
            #pragma unroll 8
            for (int k = 0; k < 32; k++) {
                float w = whh2T[k * 128 + g];
                float4 hv = *(const float4*)&h2s[k * NB + bg];
                acc[0] += hv.x * w; acc[1] += hv.y * w; acc[2] += hv.z * w; acc[3] += hv.w * w;
            }
            #pragma unroll
            for (int b = 0; b < 4; b++) g2s[(bg + b) * 128 + g] = acc[b];
        }
        __syncthreads();

        // ---- LSTM2 cell update: 256 (b,j) items ----
        {
            int b = tid >> 5, j = tid & 31;
            float gi = g2s[b * 128 + j];
            float gf = g2s[b * 128 + 32 + j];
            float gg = g2s[b * 128 + 64 + j];
            float go = g2s[b * 128 + 96 + j];
            float c = c2s[b * 32 + j];
            float nc = sigf(gf) * c + sigf(gi) * tanhf(gg);
            float h = sigf(go) * tanhf(nc);
            c2s[b * 32 + j] = nc;
            h2s[j * NB + b] = h;
        }
        __syncthreads();
    }

    // ---- qkv projection of l2_final = h2 + h1[:32] (only final step needed) ----
    #pragma unroll
    for (int r = 0; r < 3; ++r) {
        int oi = r * 256 + tid;
        int b = oi / 96, g = oi % 96;
        float acc = attn_b[g];
        #pragma unroll 8
        for (int e = 0; e < 32; e++) {
            float vv = h2s[e * NB + b] + h1s[e * NB + b];
            acc += vv * attn_w[g * 32 + e];
        }
        int m = b0 + b;
        int head = (g & 31) >> 3;
        int d = g & 7;
        if (g < 32)      q_g[head * 8192 + m * 8 + d] = acc * 0.3535533905932738f; // 1/sqrt(8)
        else if (g < 64) k_g[head * 8192 + m * 8 + d] = acc;
        else             v_g[head * 8192 + m * 8 + d] = acc;
    }
}

// =====================================================================
// Kernel 2: attention across the 1024 batch dim (one head per blockIdx.y),
//           flash-style, warp per output row, k/v in smem (stride-9 pad).
// =====================================================================
__global__ void __launch_bounds__(256, 1) attn_kernel()
{
    extern __shared__ float sm[];
    float* kh = sm;            // 1024*9
    float* vh = kh + 9216;     // 1024*9
    float* sc = vh + 9216;     // 8*1024

    const int head = blockIdx.y;
    const int tid = threadIdx.x, lane = tid & 31, w = tid >> 5;

    for (int i = tid; i < 1024 * 8; i += 256) {
        int m = i >> 3, d = i & 7;
        kh[m * 9 + d] = k_g[head * 8192 + i];
        vh[m * 9 + d] = v_g[head * 8192 + i];
    }
    __syncthreads();

    for (int il = 0; il < 4; ++il) {
        int l = blockIdx.x * 32 + w * 4 + il;
        float q[8];
        #pragma unroll
        for (int d = 0; d < 8; d++) q[d] = q_g[head * 8192 + l * 8 + d];

        float mx = -1e30f;
        for (int m = lane; m < 1024; m += 32) {
            float s = 0.f;
            #pragma unroll
            for (int d = 0; d < 8; d++) s += q[d] * kh[m * 9 + d];
            sc[w * 1024 + m] = s;
            mx = fmaxf(mx, s);
        }
        #pragma unroll
        for (int o = 16; o > 0; o >>= 1) mx = fmaxf(mx, __shfl_xor_sync(0xffffffffu, mx, o));

        float sum = 0.f;
        float acc[8];
        #pragma unroll
        for (int d = 0; d < 8; d++) acc[d] = 0.f;
        for (int m = lane; m < 1024; m += 32) {
            float e = __expf(sc[w * 1024 + m] - mx);
            sum += e;
            #pragma unroll
            for (int d = 0; d < 8; d++) acc[d] += e * vh[m * 9 + d];
        }
        #pragma unroll
        for (int o = 16; o > 0; o >>= 1) {
            sum += __shfl_xor_sync(0xffffffffu, sum, o);
            #pragma unroll
            for (int d = 0; d < 8; d++) acc[d] += __shfl_xor_sync(0xffffffffu, acc[d], o);
        }
        if (lane == 0) {
            float inv = 1.f / sum;
            #pragma unroll
            for (int d = 0; d < 8; d++) attn_g[l * 32 + head * 8 + d] = acc[d] * inv;
        }
    }
}

// =====================================================================
// Kernel 3: attn output proj + dense(32->64)+bn+relu + dense(64->32)+bn+relu
//           + dense(32->1) + sigmoid. 32 blocks x 32 batch each.
// =====================================================================
__global__ void __launch_bounds__(256, 1) mlp_kernel(
    const float* __restrict__ ow, const float* __restrict__ ob,
    const float* __restrict__ d1w, const float* __restrict__ d1b,
    const float* __restrict__ bg1, const float* __restrict__ bb1,
    const float* __restrict__ d2w, const float* __restrict__ d2b,
    const float* __restrict__ bg2, const float* __restrict__ bb2,
    const float* __restrict__ d3w, const float* __restrict__ d3b,
    float* __restrict__ out)
{
    __shared__ float owT[1024], d1T[2048], d2T[2048], d3s[32];
    __shared__ float obs[32], d1bs[64], d2bs[32], s1[64], sb1[64], s2[32], sb2[32];
    __shared__ float att[32 * 32], z1[32 * 32], z2[32 * 64], z3[32 * 32];

    const int tid = threadIdx.x;
    const int bb = blockIdx.x * 32;
    const float bnscale = rsqrtf(1.f + 1e-5f);

    for (int i = tid; i < 1024; i += 256) { int o = i & 31, e = i >> 5; owT[e * 32 + o] = ow[o * 32 + e]; }
    for (int i = tid; i < 2048; i += 256) { int o = i & 63, e = i >> 6; d1T[e * 64 + o] = d1w[o * 32 + e]; }
    for (int i = tid; i < 2048; i += 256) { int o = i & 31, e = i >> 5; d2T[e * 32 + o] = d2w[o * 64 + e]; }
    if (tid < 32) { d3s[tid] = d3w[tid]; obs[tid] = ob[tid]; d2bs[tid] = d2b[tid]; s2[tid] = bg2[tid] * bnscale; sb2[tid] = bb2[tid]; }
    if (tid < 64) { d1bs[tid] = d1b[tid]; s1[tid] = bg1[tid] * bnscale; sb1[tid] = bb1[tid]; }
    for (int i = tid; i < 1024; i += 256) att[i] = attn_g[bb * 32 + i];
    __syncthreads();

    // attention output projection
    for (int i = tid; i < 1024; i += 256) {
        int b = i >> 5, o = i & 31;
        float a = obs[o];
        #pragma unroll 8
        for (int e = 0; e < 32; e++) a += att[b * 32 + e] * owT[e * 32 + o];
        z1[b * 32 + o] = a;
    }
    __syncthreads();

    // dense1 + bn1 + relu
    for (int i = tid; i < 2048; i += 256) {
        int b = i >> 6, o = i & 63;
        float a = d1bs[o];
        #pragma unroll 8
        for (int e = 0; e < 32; e++) a += z1[b * 32 + e] * d1T[e * 64 + o];
        a = a * s1[o] + sb1[o];
        z2[b * 64 + o] = fmaxf(a, 0.f);
    }
    __syncthreads();

    // dense2 + bn2 + relu  (store transposed [o][b] for the final layer)
    for (int i = tid; i < 1024; i += 256) {
        int b = i >> 5, o = i & 31;
        float a = d2bs[o];
        #pragma unroll 8
        for (int e = 0; e < 64; e++) a += z2[b * 64 + e] * d2T[e * 32 + o];
        a = a * s2[o] + sb2[o];
        z3[o * 32 + b] = fmaxf(a, 0.f);
    }
    __syncthreads();

    // dense3 + sigmoid
    if (tid < 32) {
        int b = tid;
        float a = d3b[0];
        #pragma unroll 8
        for (int e = 0; e < 32; e++) a += z3[e * 32 + b] * d3s[e];
        out[bb + b] = 1.f / (1.f + __expf(-a));
    }
}

// =====================================================================
extern "C" void kernel_launch(void* const* d_in, const int* in_sizes, int n_in,
                              void* d_out, int out_size)
{
    const float* x      = (const float*)d_in[0];
    const float* emb_w  = (const float*)d_in[1];
    const float* emb_b  = (const float*)d_in[2];
    const float* l1_wih = (const float*)d_in[3];
    const float* l1_whh = (const float*)d_in[4];
    const float* l1_bih = (const float*)d_in[5];
    const float* l1_bhh = (const float*)d_in[6];
    const float* l2_wih = (const float*)d_in[7];
    const float* l2_whh = (const float*)d_in[8];
    const float* l2_bih = (const float*)d_in[9];
    const float* l2_bhh = (const float*)d_in[10];
    const float* attn_w = (const float*)d_in[11];
    const float* attn_b = (const float*)d_in[12];
    const float* attn_ow = (const float*)d_in[13];
    const float* attn_ob = (const float*)d_in[14];
    const float* d1_w   = (const float*)d_in[15];
    const float* d1_b   = (const float*)d_in[16];
    const float* bn1_g  = (const float*)d_in[17];
    const float* bn1_b  = (const float*)d_in[18];
    const float* d2_w   = (const float*)d_in[19];
    const float* d2_b   = (const float*)d_in[20];
    const float* bn2_g  = (const float*)d_in[21];
    const float* bn2_b  = (const float*)d_in[22];
    const float* d3_w   = (const float*)d_in[23];
    const float* d3_b   = (const float*)d_in[24];
    float* out = (float*)d_out;

    const int smem1 = 42752 * 4;   // 171008 B
    const int smem2 = (9216 * 2 + 8 * 1024) * 4; // 106496 B
    cudaFuncSetAttribute(lstm_kernel, cudaFuncAttributeMaxDynamicSharedMemorySize, smem1);
    cudaFuncSetAttribute(attn_kernel, cudaFuncAttributeMaxDynamicSharedMemorySize, smem2);

    lstm_kernel<<<128, 256, smem1>>>(x, emb_w, emb_b,
                                     l1_wih, l1_whh, l1_bih, l1_bhh,
                                     l2_wih, l2_whh, l2_bih, l2_bhh,
                                     attn_w, attn_b);
    attn_kernel<<<dim3(32, 4), 256, smem2>>>();
    mlp_kernel<<<32, 256>>>(attn_ow, attn_ob, d1_w, d1_b, bn1_g, bn1_b,
                            d2_w, d2_b, bn2_g, bn2_b, d3_w, d3_b, out);
}

// round 2
// speedup vs baseline: 1.2445x; 1.2445x over previous
#include <cuda_runtime.h>
#include <math.h>

// ---------------- global scratch (no allocations allowed) ----------------
__device__ float q_g[4 * 1024 * 8];
__device__ float k_g[4 * 1024 * 8];
__device__ float v_g[4 * 1024 * 8];
__device__ float attn_g[1024 * 32];

#define NB 8
typedef unsigned long long u64;

__device__ __forceinline__ float tanh_f(float x) {
    float y; asm("tanh.approx.f32 %0, %1;" : "=f"(y) : "f"(x)); return y;
}
__device__ __forceinline__ float sigf(float x) {
    return fmaf(0.5f, tanh_f(0.5f * x), 0.5f);
}
__device__ __forceinline__ u64 pack2(float a, float b) {
    u64 r; asm("mov.b64 %0, {%1,%2};" : "=l"(r) : "f"(a), "f"(b)); return r;
}
__device__ __forceinline__ void unpack2(u64 v, float& a, float& b) {
    asm("mov.b64 {%0,%1}, %2;" : "=f"(a), "=f"(b) : "l"(v));
}
__device__ __forceinline__ u64 fma2(u64 a, u64 b, u64 c) {
    u64 d; asm("fma.rn.f32x2 %0, %1, %2, %3;" : "=l"(d) : "l"(a), "l"(b), "l"(c)); return d;
}

// =====================================================================
// Kernel 1: fused (embedding-folded) LSTM1(32->64) + LSTM2(64->32)
//           + residual + qkv projection at the final step.
//           128 CTAs x 256 threads, 8 batch rows per CTA.
// =====================================================================
__global__ void __launch_bounds__(256, 1) lstm_kernel(
    const float* __restrict__ x,
    const float* __restrict__ emb_w, const float* __restrict__ emb_b,
    const float* __restrict__ w1, const float* __restrict__ u1,
    const float* __restrict__ b1i, const float* __restrict__ b1h,
    const float* __restrict__ w2, const float* __restrict__ u2,
    const float* __restrict__ b2i, const float* __restrict__ b2h,
    const float* __restrict__ attn_w, const float* __restrict__ attn_b)
{
    extern __shared__ float sm[];
    float* w2buf  = sm;               // 16384: stage whh1T [64][256]; later wih2T[64][128] @0, whh2T[32][128] @8192
    float* pt1s   = w2buf + 16384;    // [16][256] bias1 + wih1*(emb_b+pe[t])
    float* bias2s = pt1s + 4096;      // 128
    float* pe     = bias2s + 128;     // [16][32]
    float* embw_s = pe + 512;         // 32
    float* embb_s = embw_s + 32;      // 32
    float* xs     = embb_s + 32;      // [16][8]
    float* h1s    = xs + 128;         // [k=64][b=8]
    float* h2s    = h1s + 512;        // [j=32][b=8]
    float* g1s    = h2s + 256;        // [b=8][256]
    float* g2s    = g1s + 2048;       // [b=8][128]

    const int tid = threadIdx.x;
    const int b0 = blockIdx.x * NB;

    // ---- stage whh1 transposed [k][g] ----
    for (int i = tid; i < 64 * 256; i += 256) { int k = i >> 8, g = i & 255; w2buf[k * 256 + g] = u1[g * 64 + k]; }
    // ---- pe table, emb params ----
    for (int i = tid; i < 512; i += 256) {
        int t = i >> 5, e = i & 31;
        int half = e >> 1;
        float div = __expf(-(float)(2 * half) * (9.210340371976184f / 32.0f));
        float arg = (float)t * div;
        pe[i] = (e & 1) ? cosf(arg) : sinf(arg);
    }
    if (tid < 32) { embw_s[tid] = emb_w[tid]; embb_s[tid] = emb_b[tid]; }
    // ---- x slice, layout xs[t][b] ----
    for (int i = tid; i < NB * 16; i += 256) { int t = i >> 3, b = i & 7; xs[i] = x[(b0 + b) * 16 + t]; }
    // ---- init states ----
    for (int i = tid; i < 512; i += 256) h1s[i] = 0.f;
    if (tid < 256) h2s[tid & 255] = 0.f;  // 256 floats
    __syncthreads();

    // ---- register-resident LSTM1 recurrent weights (my gate row) ----
    float u1row[64];
    #pragma unroll
    for (int k = 0; k < 64; k++) u1row[k] = w2buf[k * 256 + tid];

    // ---- fold embedding: we1 = wih1_row . emb_w ; pt1[t] = bias1 + wih1_row . (emb_b + pe[t]) ----
    {
        float w1r[32];
        #pragma unroll
        for (int e = 0; e < 32; e++) w1r[e] = w1[tid * 32 + e];
        float we1 = 0.f;
        #pragma unroll
        for (int e = 0; e < 32; e++) we1 = fmaf(w1r[e], embw_s[e], we1);
        float bias1g = b1i[tid] + b1h[tid];
        #pragma unroll
        for (int t = 0; t < 16; t++) {
            float s = bias1g;
            #pragma unroll
            for (int e = 0; e < 32; e++) s = fmaf(w1r[e], embb_s[e] + pe[t * 32 + e], s);
            pt1s[t * 256 + tid] = s;
        }
        // stash we1 into g1s temporarily (we reuse it through a register below)
        g1s[tid] = we1;
    }
    float we1 = g1s[tid];
    const u64 we12 = pack2(we1, we1);
    __syncthreads();

    // ---- overwrite staging with LSTM2 weights (transposed) ----
    float* wih2T = w2buf;          // [64][128]
    float* whh2T = w2buf + 8192;   // [32][128]
    for (int i = tid; i < 64 * 128; i += 256) { int k = i >> 7, g = i & 127; wih2T[i] = w2[g * 64 + k]; }
    for (int i = tid; i < 32 * 128; i += 256) { int k = i >> 7, g = i & 127; whh2T[i] = u2[g * 32 + k]; }
    if (tid < 128) bias2s[tid] = b2i[tid] + b2h[tid];
    __syncthreads();

    float c1r0 = 0.f, c1r1 = 0.f, c2r = 0.f;

    for (int t = 0; t < 16; ++t) {
        // ---- Phase A: LSTM1 gate pre-activations (thread = gate, 8 batches packed) ----
        {
            float pt = pt1s[t * 256 + tid];
            u64 pt2 = pack2(pt, pt);
            const u64* xp = (const u64*)&xs[t * 8];
            u64 a0 = fma2(we12, xp[0], pt2);
            u64 a1 = fma2(we12, xp[1], pt2);
            u64 a2 = fma2(we12, xp[2], pt2);
            u64 a3 = fma2(we12, xp[3], pt2);
            #pragma unroll
            for (int k = 0; k < 64; k++) {
                u64 w2p = pack2(u1row[k], u1row[k]);
                const u64* hp = (const u64*)&h1s[k * 8];
                a0 = fma2(w2p, hp[0], a0);
                a1 = fma2(w2p, hp[1], a1);
                a2 = fma2(w2p, hp[2], a2);
                a3 = fma2(w2p, hp[3], a3);
            }
            float f0, f1;
            unpack2(a0, f0, f1); g1s[0 * 256 + tid] = f0; g1s[1 * 256 + tid] = f1;
            unpack2(a1, f0, f1); g1s[2 * 256 + tid] = f0; g1s[3 * 256 + tid] = f1;
            unpack2(a2, f0, f1); g1s[4 * 256 + tid] = f0; g1s[5 * 256 + tid] = f1;
            unpack2(a3, f0, f1); g1s[6 * 256 + tid] = f0; g1s[7 * 256 + tid] = f1;
        }
        __syncthreads();

        // ---- LSTM1 cell update: 2 cells per thread, c in registers ----
        {
            int id = tid;            // r=0
            int b = id >> 6, j = id & 63;
            float gi = g1s[b * 256 + j];
            float gf = g1s[b * 256 + 64 + j];
            float gg = g1s[b * 256 + 128 + j];
            float go = g1s[b * 256 + 192 + j];
            float nc = sigf(gf) * c1r0 + sigf(gi) * tanh_f(gg);
            c1r0 = nc;
            h1s[j * 8 + b] = sigf(go) * tanh_f(nc);

            id = 256 + tid;          // r=1
            b = id >> 6; j = id & 63;
            gi = g1s[b * 256 + j];
            gf = g1s[b * 256 + 64 + j];
            gg = g1s[b * 256 + 128 + j];
            go = g1s[b * 256 + 192 + j];
            nc = sigf(gf) * c1r1 + sigf(gi) * tanh_f(gg);
            c1r1 = nc;
            h1s[j * 8 + b] = sigf(go) * tanh_f(nc);
        }
        __syncthreads();

        // ---- Phase C: LSTM2 gate pre-activations (thread = (batch-half, gate128), 4 batches packed) ----
        {
            int g = tid & 127;
            int bg4 = (tid >> 7) * 4;
            float bv = bias2s[g];
            u64 a0 = pack2(bv, bv);
            u64 a1 = a0;
            #pragma unroll
            for (int k = 0; k < 64; k++) {
                float w = wih2T[k * 128 + g];
                u64 w2p = pack2(w, w);
                const u64* hp = (const u64*)&h1s[k * 8 + bg4];
                a0 = fma2(w2p, hp[0], a0);
                a1 = fma2(w2p, hp[1], a1);
            }
            #pragma unroll
            for (int k = 0; k < 32; k++) {
                float w = whh2T[k * 128 + g];
                u64 w2p = pack2(w, w);
                const u64* hp = (const u64*)&h2s[k * 8 + bg4];
                a0 = fma2(w2p, hp[0], a0);
                a1 = fma2(w2p, hp[1], a1);
            }
            float f0, f1;
            unpack2(a0, f0, f1); g2s[(bg4 + 0) * 128 + g] = f0; g2s[(bg4 + 1) * 128 + g] = f1;
            unpack2(a1, f0, f1); g2s[(bg4 + 2) * 128 + g] = f0; g2s[(bg4 + 3) * 128 + g] = f1;
        }
        __syncthreads();

        // ---- LSTM2 cell update: 1 cell per thread ----
        {
            int b = tid >> 5, j = tid & 31;
            float gi = g2s[b * 128 + j];
            float gf = g2s[b * 128 + 32 + j];
            float gg = g2s[b * 128 + 64 + j];
            float go = g2s[b * 128 + 96 + j];
            float nc = sigf(gf) * c2r + sigf(gi) * tanh_f(gg);
            c2r = nc;
            h2s[j * 8 + b] = sigf(go) * tanh_f(nc);
        }
        __syncthreads();
    }

    // ---- qkv projection of l2_final = h2 + h1[:32] (final step only) ----
    #pragma unroll
    for (int r = 0; r < 3; ++r) {
        int oi = r * 256 + tid;
        int b = oi / 96, g = oi % 96;
        float acc = attn_b[g];
        #pragma unroll 8
        for (int e = 0; e < 32; e++) {
            float vv = h2s[e * NB + b] + h1s[e * NB + b];
            acc = fmaf(vv, attn_w[g * 32 + e], acc);
        }
        int m = b0 + b;
        int head = (g & 31) >> 3;
        int d = g & 7;
        if (g < 32)      q_g[head * 8192 + m * 8 + d] = acc * 0.3535533905932738f; // 1/sqrt(8)
        else if (g < 64) k_g[head * 8192 + m * 8 + d] = acc;
        else             v_g[head * 8192 + m * 8 + d] = acc;
    }
}

// =====================================================================
// Kernel 2: attention across the 1024 batch dim (one head per blockIdx.y),
//           flash-style, warp per output row, k/v in smem (stride-9 pad).
// =====================================================================
__global__ void __launch_bounds__(256, 1) attn_kernel()
{
    extern __shared__ float sm[];
    float* kh = sm;            // 1024*9
    float* vh = kh + 9216;     // 1024*9
    float* sc = vh + 9216;     // 8*1024

    const int head = blockIdx.y;
    const int tid = threadIdx.x, lane = tid & 31, w = tid >> 5;

    for (int i = tid; i < 1024 * 8; i += 256) {
        int m = i >> 3, d = i & 7;
        kh[m * 9 + d] = k_g[head * 8192 + i];
        vh[m * 9 + d] = v_g[head * 8192 + i];
    }
    __syncthreads();

    for (int il = 0; il < 4; ++il) {
        int l = blockIdx.x * 32 + w * 4 + il;
        float q[8];
        #pragma unroll
        for (int d = 0; d < 8; d++) q[d] = q_g[head * 8192 + l * 8 + d];

        float mx = -1e30f;
        for (int m = lane; m < 1024; m += 32) {
            float s = 0.f;
            #pragma unroll
            for (int d = 0; d < 8; d++) s += q[d] * kh[m * 9 + d];
            sc[w * 1024 + m] = s;
            mx = fmaxf(mx, s);
        }
        #pragma unroll
        for (int o = 16; o > 0; o >>= 1) mx = fmaxf(mx, __shfl_xor_sync(0xffffffffu, mx, o));

        float sum = 0.f;
        float acc[8];
        #pragma unroll
        for (int d = 0; d < 8; d++) acc[d] = 0.f;
        for (int m = lane; m < 1024; m += 32) {
            float e = __expf(sc[w * 1024 + m] - mx);
            sum += e;
            #pragma unroll
            for (int d = 0; d < 8; d++) acc[d] += e * vh[m * 9 + d];
        }
        #pragma unroll
        for (int o = 16; o > 0; o >>= 1) {
            sum += __shfl_xor_sync(0xffffffffu, sum, o);
            #pragma unroll
            for (int d = 0; d < 8; d++) acc[d] += __shfl_xor_sync(0xffffffffu, acc[d], o);
        }
        if (lane == 0) {
            float inv = 1.f / sum;
            #pragma unroll
            for (int d = 0; d < 8; d++) attn_g[l * 32 + head * 8 + d] = acc[d] * inv;
        }
    }
}

// =====================================================================
// Kernel 3: attn output proj + dense(32->64)+bn+relu + dense(64->32)+bn+relu
//           + dense(32->1) + sigmoid. 32 blocks x 32 batch each.
// =====================================================================
__global__ void __launch_bounds__(256, 1) mlp_kernel(
    const float* __restrict__ ow, const float* __restrict__ ob,
    const float* __restrict__ d1w, const float* __restrict__ d1b,
    const float* __restrict__ bg1, const float* __restrict__ bb1,
    const float* __restrict__ d2w, const float* __restrict__ d2b,
    const float* __restrict__ bg2, const float* __restrict__ bb2,
    const float* __restrict__ d3w, const float* __restrict__ d3b,
    float* __restrict__ out)
{
    __shared__ float owT[1024], d1T[2048], d2T[2048], d3s[32];
    __shared__ float obs[32], d1bs[64], d2bs[32], s1[64], sb1[64], s2[32], sb2[32];
    __shared__ float att[32 * 32], z1[32 * 32], z2[32 * 64], z3[32 * 32];

    const int tid = threadIdx.x;
    const int bb = blockIdx.x * 32;
    const float bnscale = rsqrtf(1.f + 1e-5f);

    for (int i = tid; i < 1024; i += 256) { int o = i & 31, e = i >> 5; owT[e * 32 + o] = ow[o * 32 + e]; }
    for (int i = tid; i < 2048; i += 256) { int o = i & 63, e = i >> 6; d1T[e * 64 + o] = d1w[o * 32 + e]; }
    for (int i = tid; i < 2048; i += 256) { int o = i & 31, e = i >> 5; d2T[e * 32 + o] = d2w[o * 64 + e]; }
    if (tid < 32) { d3s[tid] = d3w[tid]; obs[tid] = ob[tid]; d2bs[tid] = d2b[tid]; s2[tid] = bg2[tid] * bnscale; sb2[tid] = bb2[tid]; }
    if (tid < 64) { d1bs[tid] = d1b[tid]; s1[tid] = bg1[tid] * bnscale; sb1[tid] = bb1[tid]; }
    for (int i = tid; i < 1024; i += 256) att[i] = attn_g[bb * 32 + i];
    __syncthreads();

    // attention output projection
    for (int i = tid; i < 1024; i += 256) {
        int b = i >> 5, o = i & 31;
        float a = obs[o];
        #pragma unroll 8
        for (int e = 0; e < 32; e++) a += att[b * 32 + e] * owT[e * 32 + o];
        z1[b * 32 + o] = a;
    }
    __syncthreads();

    // dense1 + bn1 + relu
    for (int i = tid; i < 2048; i += 256) {
        int b = i >> 6, o = i & 63;
        float a = d1bs[o];
        #pragma unroll 8
        for (int e = 0; e < 32; e++) a += z1[b * 32 + e] * d1T[e * 64 + o];
        a = a * s1[o] + sb1[o];
        z2[b * 64 + o] = fmaxf(a, 0.f);
    }
    __syncthreads();

    // dense2 + bn2 + relu  (store transposed [o][b] for the final layer)
    for (int i = tid; i < 1024; i += 256) {
        int b = i >> 5, o = i & 31;
        float a = d2bs[o];
        #pragma unroll 8
        for (int e = 0; e < 64; e++) a += z2[b * 64 + e] * d2T[e * 32 + o];
        a = a * s2[o] + sb2[o];
        z3[o * 32 + b] = fmaxf(a, 0.f);
    }
    __syncthreads();

    // dense3 + sigmoid
    if (tid < 32) {
        int b = tid;
        float a = d3b[0];
        #pragma unroll 8
        for (int e = 0; e < 32; e++) a += z3[e * 32 + b] * d3s[e];
        out[bb + b] = 1.f / (1.f + __expf(-a));
    }
}

// =====================================================================
extern "C" void kernel_launch(void* const* d_in, const int* in_sizes, int n_in,
                              void* d_out, int out_size)
{
    const float* x      = (const float*)d_in[0];
    const float* emb_w  = (const float*)d_in[1];
    const float* emb_b  = (const float*)d_in[2];
    const float* l1_wih = (const float*)d_in[3];
    const float* l1_whh = (const float*)d_in[4];
    const float* l1_bih = (const float*)d_in[5];
    const float* l1_bhh = (const float*)d_in[6];
    const float* l2_wih = (const float*)d_in[7];
    const float* l2_whh = (const float*)d_in[8];
    const float* l2_bih = (const float*)d_in[9];
    const float* l2_bhh = (const float*)d_in[10];
    const float* attn_w = (const float*)d_in[11];
    const float* attn_b = (const float*)d_in[12];
    const float* attn_ow = (const float*)d_in[13];
    const float* attn_ob = (const float*)d_in[14];
    const float* d1_w   = (const float*)d_in[15];
    const float* d1_b   = (const float*)d_in[16];
    const float* bn1_g  = (const float*)d_in[17];
    const float* bn1_b  = (const float*)d_in[18];
    const float* d2_w   = (const float*)d_in[19];
    const float* d2_b   = (const float*)d_in[20];
    const float* bn2_g  = (const float*)d_in[21];
    const float* bn2_b  = (const float*)d_in[22];
    const float* d3_w   = (const float*)d_in[23];
    const float* d3_b   = (const float*)d_in[24];
    float* out = (float*)d_out;

    const int smem1 = 25152 * 4;   // 100608 B
    const int smem2 = (9216 * 2 + 8 * 1024) * 4; // 106496 B
    cudaFuncSetAttribute(lstm_kernel, cudaFuncAttributeMaxDynamicSharedMemorySize, smem1);
    cudaFuncSetAttribute(attn_kernel, cudaFuncAttributeMaxDynamicSharedMemorySize, smem2);

    lstm_kernel<<<128, 256, smem1>>>(x, emb_w, emb_b,
                                     l1_wih, l1_whh, l1_bih, l1_bhh,
                                     l2_wih, l2_whh, l2_bih, l2_bhh,
                                     attn_w, attn_b);
    attn_kernel<<<dim3(32, 4), 256, smem2>>>();
    mlp_kernel<<<32, 256>>>(attn_ow, attn_ob, d1_w, d1_b, bn1_g, bn1_b,
                            d2_w, d2_b, bn2_g, bn2_b, d3_w, d3_b, out);
}